// round 1
// baseline (speedup 1.0000x reference)
#include <cuda_runtime.h>

#define D_DIM 1024
#define L_LAYERS 4
#define TPB 256          // one thread per 4 columns (float4)
#define GRID_BLOCKS 1024
#define RPI 2            // rows per iteration

// Scratch (no allocations allowed in kernel_launch)
__device__ float g_c4[D_DIM];   // c4[d] = b0+b1+b2+b3
__device__ float g_g[L_LAYERS]; // g[i] = (sum_{j<i} b_j) . w_i

// ---------------------------------------------------------------------------
// Prep kernel: single block, 1024 threads. Computes c4 vector and g[0..3].
// ---------------------------------------------------------------------------
__global__ void prep_kernel(const float* __restrict__ w, const float* __restrict__ b) {
    int d = threadIdx.x;  // 0..1023
    float b0 = b[d];
    float b1 = b[D_DIM + d];
    float b2 = b[2 * D_DIM + d];
    float b3 = b[3 * D_DIM + d];
    float c1 = b0;
    float c2 = c1 + b1;
    float c3 = c2 + b2;
    float c4 = c3 + b3;
    g_c4[d] = c4;

    float g1 = c1 * w[D_DIM + d];
    float g2 = c2 * w[2 * D_DIM + d];
    float g3 = c3 * w[3 * D_DIM + d];

    // warp reduce
    #pragma unroll
    for (int off = 16; off > 0; off >>= 1) {
        g1 += __shfl_down_sync(0xffffffffu, g1, off);
        g2 += __shfl_down_sync(0xffffffffu, g2, off);
        g3 += __shfl_down_sync(0xffffffffu, g3, off);
    }
    __shared__ float s[32][3];
    int warp = d >> 5, lane = d & 31;
    if (lane == 0) { s[warp][0] = g1; s[warp][1] = g2; s[warp][2] = g3; }
    __syncthreads();
    if (d < 32) {
        float v1 = s[d][0], v2 = s[d][1], v3 = s[d][2];
        #pragma unroll
        for (int off = 16; off > 0; off >>= 1) {
            v1 += __shfl_down_sync(0xffffffffu, v1, off);
            v2 += __shfl_down_sync(0xffffffffu, v2, off);
            v3 += __shfl_down_sync(0xffffffffu, v3, off);
        }
        if (d == 0) {
            g_g[0] = 0.0f;
            g_g[1] = v1;
            g_g[2] = v2;
            g_g[3] = v3;
        }
    }
}

// ---------------------------------------------------------------------------
// Main kernel: out[row] = x[row] * a4(row) + c4
//   p_i(row) = x[row] . w_i   (4 simultaneous dot products)
//   a_{i+1} = a_i * (1 + p_i) + g_i,   a_0 = 1
// Each thread owns columns [4*tid, 4*tid+4); weights live in registers and are
// reused across all rows via grid-stride. 2 rows per iteration for MLP.
// ---------------------------------------------------------------------------
__device__ __forceinline__ float dot4(float4 a, float4 b) {
    return fmaf(a.x, b.x, fmaf(a.y, b.y, fmaf(a.z, b.z, a.w * b.w)));
}

__global__ void __launch_bounds__(TPB)
cross_kernel(const float4* __restrict__ x4, const float4* __restrict__ w4,
             float4* __restrict__ out4, int n_rows) {
    const int tid  = threadIdx.x;          // 0..255
    const int warp = tid >> 5;
    const int lane = tid & 31;

    // Weights in registers (reused for every row this block processes)
    const float4 w0 = w4[0 * 256 + tid];
    const float4 w1 = w4[1 * 256 + tid];
    const float4 w2 = w4[2 * 256 + tid];
    const float4 w3 = w4[3 * 256 + tid];
    const float4 c4 = reinterpret_cast<const float4*>(g_c4)[tid];
    const float gg0 = g_g[0], gg1 = g_g[1], gg2 = g_g[2], gg3 = g_g[3];

    __shared__ float red[8][8];  // [warp][2 rows * 4 partials]

    for (int row = blockIdx.x * RPI; row < n_rows; row += gridDim.x * RPI) {
        const size_t base_a = (size_t)row * 256 + tid;
        const size_t base_b = (size_t)(row + 1) * 256 + tid;
        float4 xa = x4[base_a];
        float4 xb = x4[base_b];

        float p[8];
        p[0] = dot4(xa, w0); p[1] = dot4(xa, w1);
        p[2] = dot4(xa, w2); p[3] = dot4(xa, w3);
        p[4] = dot4(xb, w0); p[5] = dot4(xb, w1);
        p[6] = dot4(xb, w2); p[7] = dot4(xb, w3);

        // warp-level xor reduce (all lanes end with warp total)
        #pragma unroll
        for (int off = 16; off > 0; off >>= 1) {
            #pragma unroll
            for (int k = 0; k < 8; k++)
                p[k] += __shfl_xor_sync(0xffffffffu, p[k], off);
        }
        if (lane == 0) {
            #pragma unroll
            for (int k = 0; k < 8; k++) red[warp][k] = p[k];
        }
        __syncthreads();

        // every thread sums the 8 warp partials (conflict-free broadcast LDS)
        float P[8];
        #pragma unroll
        for (int k = 0; k < 8; k++) {
            float acc = red[0][k];
            #pragma unroll
            for (int wgi = 1; wgi < 8; wgi++) acc += red[wgi][k];
            P[k] = acc;
        }
        __syncthreads();  // protect red[] before next iteration overwrites

        // scalar recurrence: a = a*(1+p) + g  ==  fma(a, p, a + g)
        float aa = 1.0f, ab = 1.0f;
        aa = fmaf(aa, P[0], aa + gg0);
        aa = fmaf(aa, P[1], aa + gg1);
        aa = fmaf(aa, P[2], aa + gg2);
        aa = fmaf(aa, P[3], aa + gg3);
        ab = fmaf(ab, P[4], ab + gg0);
        ab = fmaf(ab, P[5], ab + gg1);
        ab = fmaf(ab, P[6], ab + gg2);
        ab = fmaf(ab, P[7], ab + gg3);

        float4 oa, ob;
        oa.x = fmaf(xa.x, aa, c4.x); oa.y = fmaf(xa.y, aa, c4.y);
        oa.z = fmaf(xa.z, aa, c4.z); oa.w = fmaf(xa.w, aa, c4.w);
        ob.x = fmaf(xb.x, ab, c4.x); ob.y = fmaf(xb.y, ab, c4.y);
        ob.z = fmaf(xb.z, ab, c4.z); ob.w = fmaf(xb.w, ab, c4.w);
        out4[base_a] = oa;
        out4[base_b] = ob;
    }
}

extern "C" void kernel_launch(void* const* d_in, const int* in_sizes, int n_in,
                              void* d_out, int out_size) {
    const float* x = (const float*)d_in[0];
    const float* w = (const float*)d_in[1];
    const float* b = (const float*)d_in[2];
    float* out = (float*)d_out;

    int n_rows = in_sizes[0] / D_DIM;  // 16384

    prep_kernel<<<1, 1024>>>(w, b);
    cross_kernel<<<GRID_BLOCKS, TPB>>>(
        (const float4*)x, (const float4*)w, (float4*)out, n_rows);
}

// round 2
// speedup vs baseline: 1.2348x; 1.2348x over previous
#include <cuda_runtime.h>

#define D_DIM 1024
#define D4    256          // D/4 float4s per row
#define TPB   256          // one thread per float4 column chunk
#define RPI   8            // rows per iteration
#define GRID_BLOCKS 1024

__device__ __forceinline__ float dot4(float4 a, float4 b) {
    return fmaf(a.x, b.x, fmaf(a.y, b.y, fmaf(a.z, b.z, a.w * b.w)));
}

__global__ void __launch_bounds__(TPB)
cross_kernel(const float4* __restrict__ x4,
             const float4* __restrict__ w4,
             const float4* __restrict__ b4,
             float4*       __restrict__ out4,
             int n_rows) {
    const int tid  = threadIdx.x;   // 0..255, owns columns [4*tid, 4*tid+4)
    const int warp = tid >> 5;
    const int lane = tid & 31;

    __shared__ float4 red[8][RPI];  // [warp][row] per-warp partial dots (p0..p3)
    __shared__ float  s_a[RPI];     // broadcast a_4 per row

    // ---- prologue: weights in registers + per-block g/c4 computation ----
    const float4 w0 = w4[0 * D4 + tid];
    const float4 w1 = w4[1 * D4 + tid];
    const float4 w2 = w4[2 * D4 + tid];
    const float4 w3 = w4[3 * D4 + tid];
    const float4 b0 = b4[0 * D4 + tid];
    const float4 b1 = b4[1 * D4 + tid];
    const float4 b2 = b4[2 * D4 + tid];
    const float4 b3 = b4[3 * D4 + tid];

    float4 c1, c2, c3, c4v;
    c1.x = b0.x;            c1.y = b0.y;            c1.z = b0.z;            c1.w = b0.w;
    c2.x = c1.x + b1.x;     c2.y = c1.y + b1.y;     c2.z = c1.z + b1.z;     c2.w = c1.w + b1.w;
    c3.x = c2.x + b2.x;     c3.y = c2.y + b2.y;     c3.z = c2.z + b2.z;     c3.w = c2.w + b2.w;
    c4v.x = c3.x + b3.x;    c4v.y = c3.y + b3.y;    c4v.z = c3.z + b3.z;    c4v.w = c3.w + b3.w;

    // g_i = (sum_{j<i} b_j) . w_i ; g_0 = 0
    float h1 = dot4(c1, w1);
    float h2 = dot4(c2, w2);
    float h3 = dot4(c3, w3);
    #pragma unroll
    for (int off = 16; off > 0; off >>= 1) {
        h1 += __shfl_xor_sync(0xffffffffu, h1, off);
        h2 += __shfl_xor_sync(0xffffffffu, h2, off);
        h3 += __shfl_xor_sync(0xffffffffu, h3, off);
    }
    if (lane == 0) red[warp][0] = make_float4(h1, h2, h3, 0.0f);
    __syncthreads();
    float gg1 = 0.0f, gg2 = 0.0f, gg3 = 0.0f;
    #pragma unroll
    for (int wi = 0; wi < 8; wi++) {
        float4 t = red[wi][0];
        gg1 += t.x; gg2 += t.y; gg3 += t.z;
    }
    __syncthreads();   // red[] free for reuse

    // ---- main loop: 8 rows per iteration, loads front-batched ----
    for (int row0 = blockIdx.x * RPI; row0 < n_rows; row0 += gridDim.x * RPI) {
        float4 xv[RPI];
        #pragma unroll
        for (int r = 0; r < RPI; r++) {
            if (row0 + r < n_rows)
                xv[r] = x4[(size_t)(row0 + r) * D4 + tid];
            else
                xv[r] = make_float4(0.f, 0.f, 0.f, 0.f);
        }

        #pragma unroll
        for (int r = 0; r < RPI; r++) {
            float p0 = dot4(xv[r], w0);
            float p1 = dot4(xv[r], w1);
            float p2 = dot4(xv[r], w2);
            float p3 = dot4(xv[r], w3);
            #pragma unroll
            for (int off = 16; off > 0; off >>= 1) {
                p0 += __shfl_xor_sync(0xffffffffu, p0, off);
                p1 += __shfl_xor_sync(0xffffffffu, p1, off);
                p2 += __shfl_xor_sync(0xffffffffu, p2, off);
                p3 += __shfl_xor_sync(0xffffffffu, p3, off);
            }
            if (lane == 0) red[warp][r] = make_float4(p0, p1, p2, p3);
        }
        __syncthreads();

        // lanes 0..7 (of warp 0): combine 8 warp partials for row r=tid,
        // run the scalar recurrence, broadcast a_4.
        if (tid < RPI) {
            float4 acc = red[0][tid];
            #pragma unroll
            for (int wi = 1; wi < 8; wi++) {
                float4 t = red[wi][tid];
                acc.x += t.x; acc.y += t.y; acc.z += t.z; acc.w += t.w;
            }
            // a_{i+1} = a_i*(1+p_i) + g_i = fma(a, p, a + g)
            float a = 1.0f;
            a = fmaf(a, acc.x, a);          // g0 = 0
            a = fmaf(a, acc.y, a + gg1);
            a = fmaf(a, acc.z, a + gg2);
            a = fmaf(a, acc.w, a + gg3);
            s_a[tid] = a;
        }
        __syncthreads();

        #pragma unroll
        for (int r = 0; r < RPI; r++) {
            if (row0 + r < n_rows) {
                const float a = s_a[r];
                float4 o;
                o.x = fmaf(xv[r].x, a, c4v.x);
                o.y = fmaf(xv[r].y, a, c4v.y);
                o.z = fmaf(xv[r].z, a, c4v.z);
                o.w = fmaf(xv[r].w, a, c4v.w);
                out4[(size_t)(row0 + r) * D4 + tid] = o;
            }
        }
        // next iteration's red[] writes are ordered after the combine reads by
        // the sync above; s_a reads here finish before the next combine's sync.
    }
}

extern "C" void kernel_launch(void* const* d_in, const int* in_sizes, int n_in,
                              void* d_out, int out_size) {
    const float* x = (const float*)d_in[0];
    const float* w = (const float*)d_in[1];
    const float* b = (const float*)d_in[2];
    float* out = (float*)d_out;

    int n_rows = in_sizes[0] / D_DIM;  // 16384

    cross_kernel<<<GRID_BLOCKS, TPB>>>(
        (const float4*)x, (const float4*)w, (const float4*)b,
        (float4*)out, n_rows);
}

// round 3
// speedup vs baseline: 1.5886x; 1.2865x over previous
#include <cuda_runtime.h>

#define D_DIM 1024
#define D4    256          // float4s per row
#define TPB   256          // one thread per float4 column
#define RPI   8            // rows per iteration (power of 2, 8*4=32 = warp size)
#define NBLK  444          // 148 SMs * 3 CTAs, persistent

__device__ __forceinline__ float dot4(float4 a, float4 b) {
    return fmaf(a.x, b.x, fmaf(a.y, b.y, fmaf(a.z, b.z, a.w * b.w)));
}

__global__ void __launch_bounds__(TPB, 3)
cross_kernel(const float4* __restrict__ x4,
             const float4* __restrict__ w4,
             const float4* __restrict__ b4,
             float4*       __restrict__ out4,
             int n_rows) {
    const int tid  = threadIdx.x;   // owns columns [4*tid, 4*tid+4)
    const int warp = tid >> 5;
    const int lane = tid & 31;

    __shared__ float red[8][32];    // [warp][value] per-warp reduced partials
    __shared__ float s_a[RPI];      // broadcast a_4 per row

    // ---- prologue: weights in registers, per-block g/c4 ----
    const float4 w0 = w4[tid];
    const float4 w1 = w4[D4 + tid];
    const float4 w2 = w4[2 * D4 + tid];
    const float4 w3 = w4[3 * D4 + tid];
    const float4 b0 = b4[tid];
    const float4 b1 = b4[D4 + tid];
    const float4 b2 = b4[2 * D4 + tid];
    const float4 b3 = b4[3 * D4 + tid];

    float4 c1, c2, c3, c4v;
    c1 = b0;
    c2.x = c1.x + b1.x; c2.y = c1.y + b1.y; c2.z = c1.z + b1.z; c2.w = c1.w + b1.w;
    c3.x = c2.x + b2.x; c3.y = c2.y + b2.y; c3.z = c2.z + b2.z; c3.w = c2.w + b2.w;
    c4v.x = c3.x + b3.x; c4v.y = c3.y + b3.y; c4v.z = c3.z + b3.z; c4v.w = c3.w + b3.w;

    float h1 = dot4(c1, w1);
    float h2 = dot4(c2, w2);
    float h3 = dot4(c3, w3);
    #pragma unroll
    for (int off = 16; off > 0; off >>= 1) {
        h1 += __shfl_xor_sync(0xffffffffu, h1, off);
        h2 += __shfl_xor_sync(0xffffffffu, h2, off);
        h3 += __shfl_xor_sync(0xffffffffu, h3, off);
    }
    if (lane == 0) { red[warp][0] = h1; red[warp][1] = h2; red[warp][2] = h3; }
    __syncthreads();
    float gg1 = 0.0f, gg2 = 0.0f, gg3 = 0.0f;
    #pragma unroll
    for (int wi = 0; wi < 8; wi++) {
        gg1 += red[wi][0]; gg2 += red[wi][1]; gg3 += red[wi][2];
    }
    __syncthreads();

    // ---- main loop: 8 rows / iter, 32-value butterfly reduce (31 SHFL) ----
    for (int row0 = blockIdx.x * RPI; row0 < n_rows; row0 += gridDim.x * RPI) {
        const unsigned base = (unsigned)row0 * D4 + (unsigned)tid;
        const bool full = (row0 + RPI) <= n_rows;

        // value index i = r*4 + layer; after butterfly, lane l holds total of value l
        float vals[32];
        {
            float4 xa[RPI];
            if (full) {
                #pragma unroll
                for (int r = 0; r < RPI; r++)
                    xa[r] = x4[base + (unsigned)r * D4];
            } else {
                #pragma unroll
                for (int r = 0; r < RPI; r++)
                    xa[r] = (row0 + r < n_rows) ? x4[base + (unsigned)r * D4]
                                                : make_float4(0.f, 0.f, 0.f, 0.f);
            }
            #pragma unroll
            for (int r = 0; r < RPI; r++) {
                vals[r * 4 + 0] = dot4(xa[r], w0);
                vals[r * 4 + 1] = dot4(xa[r], w1);
                vals[r * 4 + 2] = dot4(xa[r], w2);
                vals[r * 4 + 3] = dot4(xa[r], w3);
            }
        }

        #pragma unroll
        for (int o = 16; o >= 1; o >>= 1) {
            #pragma unroll
            for (int i = 0; i < o; i++) {
                float send  = (lane & o) ? vals[i] : vals[i + o];
                float other = __shfl_xor_sync(0xffffffffu, send, o);
                vals[i] = ((lane & o) ? vals[i + o] : vals[i]) + other;
            }
        }
        red[warp][lane] = vals[0];
        __syncthreads();

        if (warp == 0) {
            float tot = red[0][lane];
            #pragma unroll
            for (int wi = 1; wi < 8; wi++) tot += red[wi][lane];
            // lane l holds p(row = l>>2, layer = l&3); gather my row's 4 layers
            const int rbase = lane & ~3;
            float p0 = __shfl_sync(0xffffffffu, tot, rbase + 0);
            float p1 = __shfl_sync(0xffffffffu, tot, rbase + 1);
            float p2 = __shfl_sync(0xffffffffu, tot, rbase + 2);
            float p3 = __shfl_sync(0xffffffffu, tot, rbase + 3);
            float a = 1.0f;
            a = fmaf(a, p0, a);            // g0 = 0
            a = fmaf(a, p1, a + gg1);
            a = fmaf(a, p2, a + gg2);
            a = fmaf(a, p3, a + gg3);
            if ((lane & 3) == 0) s_a[lane >> 2] = a;
        }
        __syncthreads();

        // output: re-read x (L1-resident, loaded this iteration)
        if (full) {
            #pragma unroll
            for (int r = 0; r < RPI; r++) {
                float4 xr = x4[base + (unsigned)r * D4];
                const float a = s_a[r];
                float4 o;
                o.x = fmaf(xr.x, a, c4v.x);
                o.y = fmaf(xr.y, a, c4v.y);
                o.z = fmaf(xr.z, a, c4v.z);
                o.w = fmaf(xr.w, a, c4v.w);
                out4[base + (unsigned)r * D4] = o;
            }
        } else {
            #pragma unroll
            for (int r = 0; r < RPI; r++) {
                if (row0 + r < n_rows) {
                    float4 xr = x4[base + (unsigned)r * D4];
                    const float a = s_a[r];
                    float4 o;
                    o.x = fmaf(xr.x, a, c4v.x);
                    o.y = fmaf(xr.y, a, c4v.y);
                    o.z = fmaf(xr.z, a, c4v.z);
                    o.w = fmaf(xr.w, a, c4v.w);
                    out4[base + (unsigned)r * D4] = o;
                }
            }
        }
    }
}

extern "C" void kernel_launch(void* const* d_in, const int* in_sizes, int n_in,
                              void* d_out, int out_size) {
    const float* x = (const float*)d_in[0];
    const float* w = (const float*)d_in[1];
    const float* b = (const float*)d_in[2];
    float* out = (float*)d_out;

    int n_rows = in_sizes[0] / D_DIM;  // 16384

    cross_kernel<<<NBLK, TPB>>>(
        (const float4*)x, (const float4*)w, (const float4*)b,
        (float4*)out, n_rows);
}